// round 16
// baseline (speedup 1.0000x reference)
#include <cuda_runtime.h>
#include <cuda_bf16.h>

// Problem constants (fixed by the dataset)
#define NT 4            // B*C trees
#define NN 262144       // nodes per tree (2^18)
#define NPIX (1024*1024)
#define TOTN (NT*NN)            // 1,048,576 nodes total
#define TOTP (NT*NPIX)          // 4,194,304 pixels total

// Persistent launch shape: SM-filling, no wave quantization.
#define PBLK 1184       // 148 SMs * 8 blocks
#define PTPB 256

// Jump tables. entry = (ptr, s):
//   ptr = ancestor J levels up (0 = chain terminated at root)
//   s   = float bits of sum of c over covered segment (excl. root's c0)
// entry[0] = (0, c0) with c0 = levels[0].
__device__ int2  g_bufA[TOTN];
__device__ int2  g_bufB[TOTN];
__device__ float g_v[TOTN];     // fully materialized node values

// ---------------------------------------------------------------------------
// K1 (ILP4, grid-stride): base jump-1 table.
// c[i] = sigmoid(clamp(1000*(attr-thr),-12,12)) * (levels[i]-levels[p])
// entry[0] = (0, levels[0]).
// ---------------------------------------------------------------------------
__global__ void k_build(const float* __restrict__ attr,
                        const float* __restrict__ levels,
                        const float* __restrict__ thr,
                        const int*   __restrict__ parent)
{
    float th = __ldg(thr);
    int stride = gridDim.x * blockDim.x;
    for (int t = blockIdx.x * blockDim.x + threadIdx.x; t < TOTN / 4; t += stride) {
        int idx = t * 4;                   // NN % 4 == 0 -> same tree for all 4
        int base = idx & ~(NN - 1);
        int i0 = idx & (NN - 1);

        float4 lv = __ldg(reinterpret_cast<const float4*>(levels) + t);
        float4 at = __ldg(reinterpret_cast<const float4*>(attr) + t);
        int4   pp = __ldg(reinterpret_cast<const int4*>(parent) + t);

        float lp0 = __ldg(&levels[base + pp.x]);
        float lp1 = __ldg(&levels[base + pp.y]);
        float lp2 = __ldg(&levels[base + pp.z]);
        float lp3 = __ldg(&levels[base + pp.w]);

        float l[4] = {lv.x, lv.y, lv.z, lv.w};
        float a[4] = {at.x, at.y, at.z, at.w};
        float lp[4] = {lp0, lp1, lp2, lp3};
        int   p[4] = {pp.x, pp.y, pp.z, pp.w};

        int2 out[4];
#pragma unroll
        for (int k = 0; k < 4; k++) {
            float z = fminf(fmaxf(1000.0f * (a[k] - th), -12.0f), 12.0f);
            float s = 1.0f / (1.0f + __expf(-z));
            float c = s * (l[k] - lp[k]);
            int pk = p[k];
            if (i0 + k == 0) { pk = 0; c = l[k]; }   // root entry: (0, c0)
            out[k] = make_int2(pk, __float_as_int(c));
        }
        reinterpret_cast<int4*>(g_bufA)[t * 2 + 0] = make_int4(out[0].x, out[0].y, out[1].x, out[1].y);
        reinterpret_cast<int4*>(g_bufA)[t * 2 + 1] = make_int4(out[2].x, out[2].y, out[3].x, out[3].y);
    }
}

// ---------------------------------------------------------------------------
// K2 (ILP4, grid-stride): triple pass. out_i = e_i ∘ e[ptr_i] ∘ e[ptr[ptr_i]]
// Turns jump-1 into jump-3 (2 gathers, second dependent).
// ---------------------------------------------------------------------------
__global__ void k_triple(const int2* __restrict__ in, int2* __restrict__ out)
{
    int stride = gridDim.x * blockDim.x;
    for (int t = blockIdx.x * blockDim.x + threadIdx.x; t < TOTN / 4; t += stride) {
        int idx = t * 4;
        int base = idx & ~(NN - 1);

        int4 r0 = __ldg(reinterpret_cast<const int4*>(in) + t * 2 + 0);
        int4 r1 = __ldg(reinterpret_cast<const int4*>(in) + t * 2 + 1);
        int2 e[4] = { make_int2(r0.x, r0.y), make_int2(r0.z, r0.w),
                      make_int2(r1.x, r1.y), make_int2(r1.z, r1.w) };

        int2 b[4];
#pragma unroll
        for (int k = 0; k < 4; k++)
            b[k] = __ldg(&in[base + (e[k].x != 0 ? e[k].x : 0)]);

        int2 c[4];
#pragma unroll
        for (int k = 0; k < 4; k++) {
            int p2 = (e[k].x != 0 && b[k].x != 0) ? b[k].x : 0;
            c[k] = __ldg(&in[base + p2]);
        }

#pragma unroll
        for (int k = 0; k < 4; k++) {
            if (e[k].x != 0) {
                float s2 = __int_as_float(e[k].y) + __int_as_float(b[k].y);
                if (b[k].x != 0) {
                    e[k].x = c[k].x;
                    e[k].y = __float_as_int(s2 + __int_as_float(c[k].y));
                } else {
                    e[k].x = 0;
                    e[k].y = __float_as_int(s2);
                }
            }
        }
        reinterpret_cast<int4*>(out)[t * 2 + 0] = make_int4(e[0].x, e[0].y, e[1].x, e[1].y);
        reinterpret_cast<int4*>(out)[t * 2 + 1] = make_int4(e[2].x, e[2].y, e[3].x, e[3].y);
    }
}

// ---------------------------------------------------------------------------
// K3 (ILP4, grid-stride): materialize v[] by climbing the jump-3 table.
// v[i] = c0 + s_i + s_{ptr_i} + ...  Grid-stride averages chain-length
// variance across iterations (no ragged per-wave tails).
// ---------------------------------------------------------------------------
__global__ void k_climb3(const int2* __restrict__ jp)
{
    int stride = gridDim.x * blockDim.x;
    for (int t = blockIdx.x * blockDim.x + threadIdx.x; t < TOTN / 4; t += stride) {
        int idx = t * 4;
        int base = idx & ~(NN - 1);
        int i0 = idx & (NN - 1);

        float c0 = __int_as_float(__ldg(&jp[base].y));   // root's c0 = levels[0]

        int4 r0 = __ldg(reinterpret_cast<const int4*>(jp) + t * 2 + 0);
        int4 r1 = __ldg(reinterpret_cast<const int4*>(jp) + t * 2 + 1);
        int   j[4]   = {r0.x, r0.z, r1.x, r1.z};
        float acc[4] = {__int_as_float(r0.y), __int_as_float(r0.w),
                        __int_as_float(r1.y), __int_as_float(r1.w)};
        if (i0 == 0) { acc[0] = 0.0f; j[0] = 0; }        // node 0: v = c0 only

        while ((j[0] | j[1] | j[2] | j[3]) != 0) {
            int2 a[4];
#pragma unroll
            for (int k = 0; k < 4; k++) {
                int jj = (j[k] != 0) ? j[k] : 0;
                a[k] = __ldg(&jp[base + jj]);
            }
#pragma unroll
            for (int k = 0; k < 4; k++) {
                if (j[k] != 0) {
                    acc[k] += __int_as_float(a[k].y);
                    j[k] = a[k].x;
                }
            }
        }
#pragma unroll
        for (int k = 0; k < 4; k++) acc[k] += c0;

        reinterpret_cast<float4*>(g_v)[t] = make_float4(acc[0], acc[1], acc[2], acc[3]);
    }
}

// ---------------------------------------------------------------------------
// K4 (ILP4, grid-stride): pixel gather, ONE table lookup per pixel.
// y[p] = v[tree(p)*NN + ptn[p]].
// ---------------------------------------------------------------------------
__global__ void k_gather(const int* __restrict__ ptn, float* __restrict__ y)
{
    int stride = gridDim.x * blockDim.x;
    for (int q = blockIdx.x * blockDim.x + threadIdx.x; q < TOTP / 4; q += stride) {
        int p0 = q * 4;
        int base = (p0 >> 20) << 18;                 // tree * NN  (NPIX = 2^20)

        int4 n = __ldcs(reinterpret_cast<const int4*>(ptn) + q);
        float4 o;
        o.x = __ldg(&g_v[base + n.x]);
        o.y = __ldg(&g_v[base + n.y]);
        o.z = __ldg(&g_v[base + n.z]);
        o.w = __ldg(&g_v[base + n.w]);
        __stcs(reinterpret_cast<float4*>(y) + q, o);
    }
}

// ---------------------------------------------------------------------------
extern "C" void kernel_launch(void* const* d_in, const int* in_sizes, int n_in,
                              void* d_out, int out_size)
{
    // metadata order: x, attr_norm, levels, thr, parent, pixel_to_node
    const float* attr   = (const float*)d_in[1];
    const float* levels = (const float*)d_in[2];
    const float* thr    = (const float*)d_in[3];
    const int*   parent = (const int*)d_in[4];
    const int*   ptn    = (const int*)d_in[5];
    float*       y      = (float*)d_out;

    void *pA = nullptr, *pB = nullptr;
    cudaGetSymbolAddress(&pA, g_bufA);
    cudaGetSymbolAddress(&pB, g_bufB);
    int2* A = (int2*)pA;
    int2* B = (int2*)pB;

    k_build <<<PBLK, PTPB>>>(attr, levels, thr, parent);  // raw -> jump-1
    k_triple<<<PBLK, PTPB>>>(A, B);                       // jump-1 -> jump-3
    k_climb3<<<PBLK, PTPB>>>(B);                          // jump-3 -> full v[]
    k_gather<<<PBLK, PTPB>>>(ptn, y);                     // v[] -> pixels
}

// round 17
// speedup vs baseline: 1.0484x; 1.0484x over previous
#include <cuda_runtime.h>
#include <cuda_bf16.h>

// Problem constants (fixed by the dataset)
#define NT 4            // B*C trees
#define NN 262144       // nodes per tree (2^18)
#define NPIX (1024*1024)
#define TOTN (NT*NN)            // 1,048,576 nodes total
#define TOTP (NT*NPIX)          // 4,194,304 pixels total

// Jump tables. entry = (ptr, s):
//   ptr = ancestor J levels up (0 = chain terminated at root)
//   s   = float bits of sum of c over covered segment (excl. root's c0)
// entry[0] = (0, c0) with c0 = levels[0].
__device__ int2  g_bufA[TOTN];
__device__ int2  g_bufB[TOTN];
__device__ float g_v[TOTN];     // fully materialized node values

// ---------------------------------------------------------------------------
// K1 (ILP4): base jump-1 table. c[i] = sigmoid(clamp(1000*(attr-thr),-12,12))
//            * (levels[i]-levels[p]);  entry[0] = (0, levels[0]).
// ---------------------------------------------------------------------------
__global__ void k_build(const float* __restrict__ attr,
                        const float* __restrict__ levels,
                        const float* __restrict__ thr,
                        const int*   __restrict__ parent)
{
    int t = blockIdx.x * blockDim.x + threadIdx.x;
    if (t >= TOTN / 4) return;
    int idx = t * 4;                       // NN % 4 == 0 -> same tree for all 4
    int base = idx & ~(NN - 1);
    int i0 = idx & (NN - 1);

    float4 lv = __ldg(reinterpret_cast<const float4*>(levels) + t);
    float4 at = __ldg(reinterpret_cast<const float4*>(attr) + t);
    int4   pp = __ldg(reinterpret_cast<const int4*>(parent) + t);
    float  th = __ldg(thr);

    float lp0 = __ldg(&levels[base + pp.x]);
    float lp1 = __ldg(&levels[base + pp.y]);
    float lp2 = __ldg(&levels[base + pp.z]);
    float lp3 = __ldg(&levels[base + pp.w]);

    float l[4] = {lv.x, lv.y, lv.z, lv.w};
    float a[4] = {at.x, at.y, at.z, at.w};
    float lp[4] = {lp0, lp1, lp2, lp3};
    int   p[4] = {pp.x, pp.y, pp.z, pp.w};

    int2 out[4];
#pragma unroll
    for (int k = 0; k < 4; k++) {
        float z = fminf(fmaxf(1000.0f * (a[k] - th), -12.0f), 12.0f);
        float s = 1.0f / (1.0f + __expf(-z));
        float c = s * (l[k] - lp[k]);
        int pk = p[k];
        if (i0 + k == 0) { pk = 0; c = l[k]; }     // root entry: (0, c0)
        out[k] = make_int2(pk, __float_as_int(c));
    }
    reinterpret_cast<int4*>(g_bufA)[t * 2 + 0] = make_int4(out[0].x, out[0].y, out[1].x, out[1].y);
    reinterpret_cast<int4*>(g_bufA)[t * 2 + 1] = make_int4(out[2].x, out[2].y, out[3].x, out[3].y);
}

// ---------------------------------------------------------------------------
// K2 (ILP4): triple pass. out_i = e_i ∘ e[ptr_i] ∘ e[ptr[ptr_i]]
// Turns jump-1 into jump-3 (2 gathers, second dependent).
// ---------------------------------------------------------------------------
__global__ void k_triple(const int2* __restrict__ in, int2* __restrict__ out)
{
    int t = blockIdx.x * blockDim.x + threadIdx.x;
    if (t >= TOTN / 4) return;
    int idx = t * 4;
    int base = idx & ~(NN - 1);

    int4 r0 = __ldg(reinterpret_cast<const int4*>(in) + t * 2 + 0);
    int4 r1 = __ldg(reinterpret_cast<const int4*>(in) + t * 2 + 1);
    int2 e[4] = { make_int2(r0.x, r0.y), make_int2(r0.z, r0.w),
                  make_int2(r1.x, r1.y), make_int2(r1.z, r1.w) };

    int2 b[4];
#pragma unroll
    for (int k = 0; k < 4; k++)
        b[k] = __ldg(&in[base + (e[k].x != 0 ? e[k].x : 0)]);

    int2 c[4];
#pragma unroll
    for (int k = 0; k < 4; k++) {
        int p2 = (e[k].x != 0 && b[k].x != 0) ? b[k].x : 0;
        c[k] = __ldg(&in[base + p2]);
    }

#pragma unroll
    for (int k = 0; k < 4; k++) {
        if (e[k].x != 0) {
            float s2 = __int_as_float(e[k].y) + __int_as_float(b[k].y);
            if (b[k].x != 0) {
                e[k].x = c[k].x;
                e[k].y = __float_as_int(s2 + __int_as_float(c[k].y));
            } else {
                e[k].x = 0;
                e[k].y = __float_as_int(s2);
            }
        }
    }
    reinterpret_cast<int4*>(out)[t * 2 + 0] = make_int4(e[0].x, e[0].y, e[1].x, e[1].y);
    reinterpret_cast<int4*>(out)[t * 2 + 1] = make_int4(e[2].x, e[2].y, e[3].x, e[3].y);
}

// ---------------------------------------------------------------------------
// K3 (ILP4): materialize v[] by climbing the jump-3 table.
// v[i] = c0 + s_i + s_{ptr_i} + ...
// ---------------------------------------------------------------------------
__global__ void k_climb3(const int2* __restrict__ jp)
{
    int t = blockIdx.x * blockDim.x + threadIdx.x;
    if (t >= TOTN / 4) return;
    int idx = t * 4;
    int base = idx & ~(NN - 1);
    int i0 = idx & (NN - 1);

    float c0 = __int_as_float(__ldg(&jp[base].y));   // root's c0 = levels[0]

    int4 r0 = __ldg(reinterpret_cast<const int4*>(jp) + t * 2 + 0);
    int4 r1 = __ldg(reinterpret_cast<const int4*>(jp) + t * 2 + 1);
    int   j[4]   = {r0.x, r0.z, r1.x, r1.z};
    float acc[4] = {__int_as_float(r0.y), __int_as_float(r0.w),
                    __int_as_float(r1.y), __int_as_float(r1.w)};
    if (i0 == 0) { acc[0] = 0.0f; j[0] = 0; }        // node 0: v = c0 only

    while ((j[0] | j[1] | j[2] | j[3]) != 0) {
        int2 a[4];
#pragma unroll
        for (int k = 0; k < 4; k++) {
            int jj = (j[k] != 0) ? j[k] : 0;
            a[k] = __ldg(&jp[base + jj]);
        }
#pragma unroll
        for (int k = 0; k < 4; k++) {
            if (j[k] != 0) {
                acc[k] += __int_as_float(a[k].y);
                j[k] = a[k].x;
            }
        }
    }
#pragma unroll
    for (int k = 0; k < 4; k++) acc[k] += c0;

    reinterpret_cast<float4*>(g_v)[t] = make_float4(acc[0], acc[1], acc[2], acc[3]);
}

// ---------------------------------------------------------------------------
// K4: pixel gather, exactly ONE table lookup per pixel.
// y[p] = v[tree(p)*NN + ptn[p]].  Streams use evict-first hints to keep
// L1 for the v-table.
// ---------------------------------------------------------------------------
__global__ void k_gather(const int* __restrict__ ptn, float* __restrict__ y)
{
    int q = blockIdx.x * blockDim.x + threadIdx.x;   // quad index
    if (q >= TOTP / 4) return;
    int p0 = q * 4;
    int base = (p0 >> 20) << 18;                     // tree * NN  (NPIX = 2^20)

    int4 n = __ldcs(reinterpret_cast<const int4*>(ptn) + q);
    float4 o;
    o.x = __ldg(&g_v[base + n.x]);
    o.y = __ldg(&g_v[base + n.y]);
    o.z = __ldg(&g_v[base + n.z]);
    o.w = __ldg(&g_v[base + n.w]);
    __stcs(reinterpret_cast<float4*>(y) + q, o);
}

// ---------------------------------------------------------------------------
extern "C" void kernel_launch(void* const* d_in, const int* in_sizes, int n_in,
                              void* d_out, int out_size)
{
    // metadata order: x, attr_norm, levels, thr, parent, pixel_to_node
    const float* attr   = (const float*)d_in[1];
    const float* levels = (const float*)d_in[2];
    const float* thr    = (const float*)d_in[3];
    const int*   parent = (const int*)d_in[4];
    const int*   ptn    = (const int*)d_in[5];
    float*       y      = (float*)d_out;

    void *pA = nullptr, *pB = nullptr;
    cudaGetSymbolAddress(&pA, g_bufA);
    cudaGetSymbolAddress(&pB, g_bufB);
    int2* A = (int2*)pA;
    int2* B = (int2*)pB;

    const int TPB = 256;
    const int gbN4 = (TOTN / 4) / TPB;

    k_build<<<gbN4, TPB>>>(attr, levels, thr, parent);   // raw -> jump-1
    k_triple<<<gbN4, TPB>>>(A, B);                       // jump-1 -> jump-3
    k_climb3<<<gbN4, TPB>>>(B);                          // jump-3 -> full v[]

    const int gbP = (TOTP / 4) / TPB;
    k_gather<<<gbP, TPB>>>(ptn, y);
}